// round 5
// baseline (speedup 1.0000x reference)
#include <cuda_runtime.h>
#include <math.h>

#define W    512
#define HGT  512
#define HW   (512*512)
#define TW   64
#define TH   64
#define RMAX 10
#define SW   84               // TW + 2*RMAX
#define SH   (TH + 2*RMAX)    // 84
#define MW   68               // padded mid width (17 float4, odd -> conflict-free)
#define NKER 21
#define NTH  256
#define WTOT 243
#define MIDSZ (SH*MW)
#define SMEM_BYTES ((SH*SW + 2*MIDSZ)*4 + WTOT*8)

typedef unsigned long long u64;

// KSIZES reproduced exactly from the reference (incl. i=19 fp edge -> k=21)
__constant__ int   c_KS[NKER]  = {3,3,3,5,5,7,7,9,9,11,11,13,13,15,15,17,17,19,19,21,21};
__constant__ int   c_OFF[NKER] = {0,3,6,9,14,19,26,33,42,51,62,73,86,99,114,129,146,163,182,201,222};
__constant__ float c_SIG[NKER] = {0.500f,0.525f,0.550f,0.575f,0.600f,0.625f,0.650f,0.675f,0.700f,0.725f,
                                  0.750f,0.775f,0.800f,0.825f,0.850f,0.875f,0.900f,0.925f,0.950f,0.975f,1.000f};
// filter-index groups with ~equal total cost (sumK = 123 vs 120)
__constant__ int   c_G0[9]  = {0,1,2,15,16,17,18,19,20};
__constant__ int   c_G1[12] = {3,4,5,6,7,8,9,10,11,12,13,14};

__device__ __forceinline__ u64 pack2(float lo, float hi) {
    u64 d; asm("mov.b64 %0, {%1, %2};" : "=l"(d) : "f"(lo), "f"(hi)); return d;
}
__device__ __forceinline__ void fma2(u64& d, u64 a, u64 b) {
    asm("fma.rn.f32x2 %0, %1, %2, %0;" : "+l"(d) : "l"(a), "l"(b));
}
union F2 { u64 u; float2 f; };

__device__ __forceinline__ int refl(int v) {
    if (v < 0)    v = -v;
    if (v >= 512) v = 1022 - v;
    return v;
}

// ---- horizontal pass: s_in -> s_mid. 1 mid row x 16 cols per task. ----
template<int K>
__device__ __forceinline__ void blur_h(const float* __restrict__ s_in,
                                       float* __restrict__ s_mid,
                                       const u64* __restrict__ w2, int tid) {
    constexpr int R     = (K - 1) / 2;
    constexpr int MROWS = TH + 2 * R;        // <= 84
    constexpr int HK    = (K + 1) / 2;
    constexpr int D     = (RMAX - R) & 3;
    constexpr int COL0  = (RMAX - R) - D;
    constexpr int NV    = D + K + 15;
    constexpr int NW4   = (NV + 3) / 4;
    constexpr int ROW0  = RMAX - R;

    u64 wr[HK];
    #pragma unroll
    for (int j = 0; j < HK; ++j) wr[j] = w2[j];

    int lane = tid & 31, wid = tid >> 5;
    int lr = lane & 7, cg = lane >> 3;       // row-in-chunk, 16-col group
    constexpr int NCH = (MROWS + 7) / 8;
    #pragma unroll
    for (int ch = wid; ch < NCH; ch += 8) {
        int r = ch * 8 + lr;
        if (r < MROWS) {
            const float4* src = (const float4*)(s_in + (r + ROW0) * SW + cg * 16 + COL0);
            float v[NW4 * 4];
            #pragma unroll
            for (int i = 0; i < NW4; ++i) *(float4*)&v[4 * i] = src[i];
            u64 a[8];
            #pragma unroll
            for (int g = 0; g < 8; ++g) a[g] = 0;
            #pragma unroll
            for (int m = 0; m < K + 14; ++m) {
                u64 p = pack2(v[D + m], v[D + m + 1]);
                #pragma unroll
                for (int g = 0; g < 8; ++g) {
                    int j = m - 2 * g;
                    if (j >= 0 && j < K)
                        fma2(a[g], wr[(j < HK) ? j : (K - 1 - j)], p);
                }
            }
            float4* dst = (float4*)(s_mid + r * MW + cg * 16);
            #pragma unroll
            for (int g = 0; g < 4; ++g) {
                F2 f0, f1; f0.u = a[2 * g]; f1.u = a[2 * g + 1];
                dst[g] = make_float4(f0.f.x, f0.f.y, f1.f.x, f1.f.y);
            }
        }
    }
}

// ---- vertical pass: s_mid -> gmem. 8 rows x 2 cols per thread. ----
template<int K>
__device__ __forceinline__ void blur_v(const float* __restrict__ s_mid,
                                       const u64* __restrict__ w2,
                                       float* __restrict__ outp,
                                       int x0, int y0, int tid) {
    constexpr int HK = (K + 1) / 2;
    u64 wr[HK];
    #pragma unroll
    for (int j = 0; j < HK; ++j) wr[j] = w2[j];

    int cp = tid & 31;
    int r0 = (tid >> 5) * 8;
    const float* mp = s_mid + r0 * MW + cp * 2;
    u64 acc[8];
    #pragma unroll
    for (int r = 0; r < 8; ++r) acc[r] = 0;
    #pragma unroll
    for (int m = 0; m < K + 7; ++m) {
        u64 val = *(const u64*)(mp + m * MW);
        #pragma unroll
        for (int r = 0; r < 8; ++r) {
            int j = m - r;
            if (j >= 0 && j < K)
                fma2(acc[r], wr[(j < HK) ? j : (K - 1 - j)], val);
        }
    }
    float* o = outp + (size_t)(y0 + r0) * W + (x0 + cp * 2);
    #pragma unroll
    for (int r = 0; r < 8; ++r) {
        F2 f; f.u = acc[r];
        *(float2*)(o + (size_t)r * W) = f.f;
    }
}

__device__ __forceinline__ void do_h(int K, const float* s_in, float* s_mid,
                                     const u64* w2, int tid) {
    switch (K) {
        case 3:  blur_h<3 >(s_in, s_mid, w2, tid); break;
        case 5:  blur_h<5 >(s_in, s_mid, w2, tid); break;
        case 7:  blur_h<7 >(s_in, s_mid, w2, tid); break;
        case 9:  blur_h<9 >(s_in, s_mid, w2, tid); break;
        case 11: blur_h<11>(s_in, s_mid, w2, tid); break;
        case 13: blur_h<13>(s_in, s_mid, w2, tid); break;
        case 15: blur_h<15>(s_in, s_mid, w2, tid); break;
        case 17: blur_h<17>(s_in, s_mid, w2, tid); break;
        case 19: blur_h<19>(s_in, s_mid, w2, tid); break;
        case 21: blur_h<21>(s_in, s_mid, w2, tid); break;
    }
}
__device__ __forceinline__ void do_v(int K, const float* s_mid, const u64* w2,
                                     float* outp, int x0, int y0, int tid) {
    switch (K) {
        case 3:  blur_v<3 >(s_mid, w2, outp, x0, y0, tid); break;
        case 5:  blur_v<5 >(s_mid, w2, outp, x0, y0, tid); break;
        case 7:  blur_v<7 >(s_mid, w2, outp, x0, y0, tid); break;
        case 9:  blur_v<9 >(s_mid, w2, outp, x0, y0, tid); break;
        case 11: blur_v<11>(s_mid, w2, outp, x0, y0, tid); break;
        case 13: blur_v<13>(s_mid, w2, outp, x0, y0, tid); break;
        case 15: blur_v<15>(s_mid, w2, outp, x0, y0, tid); break;
        case 17: blur_v<17>(s_mid, w2, outp, x0, y0, tid); break;
        case 19: blur_v<19>(s_mid, w2, outp, x0, y0, tid); break;
        case 21: blur_v<21>(s_mid, w2, outp, x0, y0, tid); break;
    }
}

__global__ void __launch_bounds__(NTH, 3)
gauss_fused(const float* __restrict__ x, float* __restrict__ out) {
    extern __shared__ float smem[];
    float* s_in  = smem;                          // SH*SW
    float* s_m0  = smem + SH * SW;                // mid buffer 0
    float* s_m1  = s_m0 + MIDSZ;                  // mid buffer 1
    u64*   s_w2  = (u64*)(s_m1 + MIDSZ);

    int tid = threadIdx.x;

    // per-CTA weight computation (graph-capturable)
    if (tid < NKER) {
        int K = c_KS[tid];
        float sg = c_SIG[tid];
        int off = c_OFF[tid];
        float s2 = 2.0f * sg * sg;
        int h = K / 2;
        float sum = 0.0f;
        for (int j = 0; j < K; ++j) { float d = (float)(j - h); sum += expf(-d * d / s2); }
        for (int j = 0; j < K; ++j) {
            float d = (float)(j - h);
            float w = expf(-d * d / s2) / sum;
            s_w2[off + j] = pack2(w, w);
        }
    }

    int z = blockIdx.z;                  // [0,48): group*24 + plane
    int group = z >= 24;
    int plane = group ? z - 24 : z;      // b*3 + c
    int b = plane / 3, c = plane - 3 * b;
    int x0 = blockIdx.x * TW, y0 = blockIdx.y * TH;
    const float* xin = x + (size_t)plane * HW;

    // load 84x84 halo tile once (reflect), reused by this group's filters
    for (int idx = tid; idx < SH * SW; idx += NTH) {
        int ly = idx / SW, lx = idx - ly * SW;
        int gy = refl(y0 + ly - RMAX);
        int gx = refl(x0 + lx - RMAX);
        s_in[idx] = xin[gy * W + gx];
    }
    __syncthreads();

    const int* list = group ? c_G1 : c_G0;
    int cnt = group ? 12 : 9;

    // software-pipelined: H_t || V_{t-1}, double-buffered mid, 1 barrier/iter
    int pK = 0; const u64* pW = 0; float* pOut = 0; const float* pMid = 0;
    #pragma unroll 1
    for (int t = 0; t < cnt; ++t) {
        int i = list[t];
        int K = c_KS[i];
        float* mid = (t & 1) ? s_m1 : s_m0;
        const u64* w2 = s_w2 + c_OFF[i];
        do_h(K, s_in, mid, w2, tid);
        if (t) do_v(pK, pMid, pW, pOut, x0, y0, tid);
        __syncthreads();
        pK = K; pW = w2; pMid = mid;
        pOut = out + (size_t)(b * 66 + 3 + 3 * i + c) * HW;
    }
    do_v(pK, pMid, pW, pOut, x0, y0, tid);
}

// identity channels: out[b][0..2] = x[b][0..2]
__global__ void copy_id(const float* __restrict__ x, float* __restrict__ out) {
    int plane = blockIdx.y;              // b*3 + c
    int b = plane / 3, c = plane - 3 * b;
    const float4* src = (const float4*)(x + (size_t)plane * HW);
    float4*       dst = (float4*)(out + (size_t)(b * 66 + c) * HW);
    int i = blockIdx.x * blockDim.x + threadIdx.x;
    dst[i] = src[i];
}

extern "C" void kernel_launch(void* const* d_in, const int* in_sizes, int n_in,
                              void* d_out, int out_size) {
    const float* x = (const float*)d_in[0];
    float* out = (float*)d_out;

    cudaFuncSetAttribute(gauss_fused, cudaFuncAttributeMaxDynamicSharedMemorySize, SMEM_BYTES);

    dim3 cgrid(HW / 4 / NTH, 24);
    copy_id<<<cgrid, NTH>>>(x, out);

    dim3 grid(W / TW, HGT / TH, 48);     // 8 x 8 x (24 planes x 2 filter groups)
    gauss_fused<<<grid, NTH, SMEM_BYTES>>>(x, out);
}

// round 6
// speedup vs baseline: 1.1224x; 1.1224x over previous
#include <cuda_runtime.h>
#include <math.h>

#define W    512
#define HGT  512
#define HW   (512*512)
#define TW   64
#define TH   64
#define RMAX 10
#define SW   84               // TW + 2*RMAX
#define SH   (TH + 2*RMAX)    // 84
#define MW   68               // padded mid width
#define NKER 21
#define NTH  256
#define WTOT 243
#define SMEM_BYTES ((SH*SW + SH*MW)*4 + WTOT*8)

typedef unsigned long long u64;

// KSIZES reproduced exactly from the reference (incl. i=19 fp edge -> k=21)
__constant__ int   c_KS[NKER]  = {3,3,3,5,5,7,7,9,9,11,11,13,13,15,15,17,17,19,19,21,21};
__constant__ int   c_OFF[NKER] = {0,3,6,9,14,19,26,33,42,51,62,73,86,99,114,129,146,163,182,201,222};
__constant__ float c_SIG[NKER] = {0.500f,0.525f,0.550f,0.575f,0.600f,0.625f,0.650f,0.675f,0.700f,0.725f,
                                  0.750f,0.775f,0.800f,0.825f,0.850f,0.875f,0.900f,0.925f,0.950f,0.975f,1.000f};

__device__ __forceinline__ u64 pack2(float lo, float hi) {
    u64 d; asm("mov.b64 %0, {%1, %2};" : "=l"(d) : "f"(lo), "f"(hi)); return d;
}
__device__ __forceinline__ void fma2(u64& d, u64 a, u64 b) {
    asm("fma.rn.f32x2 %0, %1, %2, %0;" : "+l"(d) : "l"(a), "l"(b));
}
union F2 { u64 u; float2 f; };

__device__ __forceinline__ int refl(int v) {
    if (v < 0)    v = -v;
    if (v >= 512) v = 1022 - v;
    return v;
}

// One separable blur of the resident tile. K compile-time.
template<int K>
__device__ __forceinline__ void blur_one(const float* __restrict__ s_in,
                                         float* __restrict__ s_mid,
                                         const u64* __restrict__ w2,
                                         float* __restrict__ outp,
                                         int x0, int y0, int tid) {
    constexpr int R     = (K - 1) / 2;
    constexpr int MROWS = TH + 2 * R;        // <= 84
    constexpr int HK    = (K + 1) / 2;
    constexpr int D     = (RMAX - R) & 3;
    constexpr int COL0  = (RMAX - R) - D;
    constexpr int NV    = D + K + 15;        // total window floats
    constexpr int NW4   = (NV + 3) / 4;
    constexpr int ROW0  = RMAX - R;

    // weights -> registers (symmetric half), packed f32x2
    u64 wr[HK];
    #pragma unroll
    for (int j = 0; j < HK; ++j) wr[j] = w2[j];

    // ---- horizontal: 1 mid row x 16 cols per task, rolling 8-float window ----
    {
        int lane = tid & 31, wid = tid >> 5;
        int lr = lane & 7, cg = lane >> 3;
        constexpr int NCH = (MROWS + 7) / 8;
        for (int ch = wid; ch < NCH; ch += 8) {
            int r = ch * 8 + lr;
            if (r < MROWS) {
                const float4* src = (const float4*)(s_in + (r + ROW0) * SW + cg * 16 + COL0);
                float vb[8];
                *(float4*)&vb[0] = src[0];
                *(float4*)&vb[4] = src[1];
                u64 a[8];
                #pragma unroll
                for (int g = 0; g < 8; ++g) a[g] = 0;
                #pragma unroll
                for (int m = 0; m < K + 14; ++m) {
                    constexpr_hint:;
                    int e = D + m + 1;
                    if ((e & 3) == 0 && e >= 8 && (e >> 2) < NW4)
                        *(float4*)&vb[(e >> 2 & 1) * 4] = src[e >> 2];
                    u64 p = pack2(vb[(D + m) & 7], vb[(D + m + 1) & 7]);
                    #pragma unroll
                    for (int g = 0; g < 8; ++g) {
                        int j = m - 2 * g;
                        if (j >= 0 && j < K)
                            fma2(a[g], wr[(j < HK) ? j : (K - 1 - j)], p);
                    }
                }
                float4* dst = (float4*)(s_mid + r * MW + cg * 16);
                #pragma unroll
                for (int g = 0; g < 4; ++g) {
                    F2 f0, f1; f0.u = a[2 * g]; f1.u = a[2 * g + 1];
                    dst[g] = make_float4(f0.f.x, f0.f.y, f1.f.x, f1.f.y);
                }
            }
        }
    }
    __syncthreads();

    // ---- vertical: 8 rows x 2 cols per thread ----
    {
        int cp = tid & 31;
        int r0 = (tid >> 5) * 8;
        const float* mp = s_mid + r0 * MW + cp * 2;
        u64 acc[8];
        #pragma unroll
        for (int r = 0; r < 8; ++r) acc[r] = 0;
        #pragma unroll
        for (int m = 0; m < K + 7; ++m) {
            u64 val = *(const u64*)(mp + m * MW);
            #pragma unroll
            for (int r = 0; r < 8; ++r) {
                int j = m - r;
                if (j >= 0 && j < K)
                    fma2(acc[r], wr[(j < HK) ? j : (K - 1 - j)], val);
            }
        }
        float* o = outp + (size_t)(y0 + r0) * W + (x0 + cp * 2);
        #pragma unroll
        for (int r = 0; r < 8; ++r) {
            F2 f; f.u = acc[r];
            *(float2*)(o + (size_t)r * W) = f.f;
        }
    }
    __syncthreads();
}

__global__ void __launch_bounds__(NTH, 4)
gauss_fused(const float* __restrict__ x, float* __restrict__ out) {
    extern __shared__ float smem[];
    float* s_in  = smem;                         // SH*SW
    float* s_mid = smem + SH * SW;               // SH*MW
    u64*   s_w2  = (u64*)(smem + SH * SW + SH * MW);

    int tid = threadIdx.x;

    // per-CTA weight computation (graph-capturable)
    if (tid < NKER) {
        int K = c_KS[tid];
        float sg = c_SIG[tid];
        int off = c_OFF[tid];
        float s2 = 2.0f * sg * sg;
        int h = K / 2;
        float sum = 0.0f;
        for (int j = 0; j < K; ++j) { float d = (float)(j - h); sum += expf(-d * d / s2); }
        for (int j = 0; j < K; ++j) {
            float d = (float)(j - h);
            float w = expf(-d * d / s2) / sum;
            s_w2[off + j] = pack2(w, w);
        }
    }

    int z = blockIdx.z;                 // b*3 + c
    int b = z / 3, c = z - 3 * b;
    int x0 = blockIdx.x * TW, y0 = blockIdx.y * TH;
    const float* xin = x + (size_t)z * HW;

    // load 84x84 halo tile once, reused by all 21 filters
    bool interior = (x0 != 0) && (x0 != W - TW) && (y0 != 0) && (y0 != HGT - TH);
    if (interior) {
        // fast path: no reflection, vectorized float2 loads
        const float* base = xin + (size_t)(y0 - RMAX) * W + (x0 - RMAX);
        for (int idx = tid; idx < SH * (SW / 2); idx += NTH) {
            int ly = idx / (SW / 2), lx = idx - ly * (SW / 2);
            *(float2*)(s_in + ly * SW + lx * 2) =
                *(const float2*)(base + ly * W + lx * 2);
        }
    } else {
        for (int idx = tid; idx < SH * SW; idx += NTH) {
            int ly = idx / SW, lx = idx - ly * SW;
            int gy = refl(y0 + ly - RMAX);
            int gx = refl(x0 + lx - RMAX);
            s_in[idx] = xin[gy * W + gx];
        }
    }
    __syncthreads();

    #pragma unroll 1
    for (int i = 0; i < NKER; ++i) {
        float* outp = out + (size_t)(b * 66 + 3 + 3 * i + c) * HW;
        const u64* w2 = s_w2 + c_OFF[i];
        switch (c_KS[i]) {
            case 3:  blur_one<3 >(s_in, s_mid, w2, outp, x0, y0, tid); break;
            case 5:  blur_one<5 >(s_in, s_mid, w2, outp, x0, y0, tid); break;
            case 7:  blur_one<7 >(s_in, s_mid, w2, outp, x0, y0, tid); break;
            case 9:  blur_one<9 >(s_in, s_mid, w2, outp, x0, y0, tid); break;
            case 11: blur_one<11>(s_in, s_mid, w2, outp, x0, y0, tid); break;
            case 13: blur_one<13>(s_in, s_mid, w2, outp, x0, y0, tid); break;
            case 15: blur_one<15>(s_in, s_mid, w2, outp, x0, y0, tid); break;
            case 17: blur_one<17>(s_in, s_mid, w2, outp, x0, y0, tid); break;
            case 19: blur_one<19>(s_in, s_mid, w2, outp, x0, y0, tid); break;
            case 21: blur_one<21>(s_in, s_mid, w2, outp, x0, y0, tid); break;
        }
    }
}

// identity channels: out[b][0..2] = x[b][0..2]
__global__ void copy_id(const float* __restrict__ x, float* __restrict__ out) {
    int plane = blockIdx.y;             // b*3 + c
    int b = plane / 3, c = plane - 3 * b;
    const float4* src = (const float4*)(x + (size_t)plane * HW);
    float4*       dst = (float4*)(out + (size_t)(b * 66 + c) * HW);
    int i = blockIdx.x * blockDim.x + threadIdx.x;
    dst[i] = src[i];
}

extern "C" void kernel_launch(void* const* d_in, const int* in_sizes, int n_in,
                              void* d_out, int out_size) {
    const float* x = (const float*)d_in[0];
    float* out = (float*)d_out;

    cudaFuncSetAttribute(gauss_fused, cudaFuncAttributeMaxDynamicSharedMemorySize, SMEM_BYTES);

    dim3 cgrid(HW / 4 / NTH, 24);
    copy_id<<<cgrid, NTH>>>(x, out);

    dim3 grid(W / TW, HGT / TH, 24);    // 8 x 8 x 24
    gauss_fused<<<grid, NTH, SMEM_BYTES>>>(x, out);
}